// round 3
// baseline (speedup 1.0000x reference)
#include <cuda_runtime.h>
#include <math.h>

// Problem constants
#define B_   2
#define S_   2048
#define H_   2048
#define NH_  16
#define NKV_ 4
#define HD_  128
#define M_   (B_*S_)          // 4096 rows of tokens

// ---------------------------------------------------------------------------
// Scratch (device globals; no allocation allowed)
// ---------------------------------------------------------------------------
__device__ float g_q[(size_t)M_ * NH_ * HD_];     // 4096 x 2048
__device__ float g_k[(size_t)M_ * NKV_ * HD_];    // 4096 x 512
__device__ float g_v[(size_t)M_ * NKV_ * HD_];    // 4096 x 512
__device__ float g_attn[(size_t)M_ * NH_ * HD_];  // 4096 x 2048
__device__ float g_tab[S_ * 64 * 2];              // RoPE cos/sin table

// ---------------------------------------------------------------------------
// SGEMM: C[M,N] = A[M,K] @ B[K,N], all fp32 row-major.
// 128x128 block tile, BK=8, 256 threads, 8x8 per-thread microtile.
// asel==1 -> A = g_attn;  csel: 0=C param, 1=g_q, 2=g_k, 3=g_v
// ---------------------------------------------------------------------------
__global__ __launch_bounds__(256) void sgemm_kernel(
    const float* __restrict__ A, const float* __restrict__ Bm,
    float* __restrict__ C, int M, int N, int K, int asel, int csel)
{
    if (asel == 1) A = g_attn;
    if (csel == 1) C = g_q;
    else if (csel == 2) C = g_k;
    else if (csel == 3) C = g_v;

    __shared__ float As[8][128];
    __shared__ float Bs[8][128];

    int t  = threadIdx.x;
    int tx = t & 15, ty = t >> 4;
    int bn = blockIdx.x * 128, bm = blockIdx.y * 128;

    int aRow = t >> 1, aK = (t & 1) * 4;    // A: 128 rows x 8 k
    int bK   = t >> 5, bCol = (t & 31) * 4; // B: 8 k x 128 cols

    const float* Ap = A  + (size_t)(bm + aRow) * K + aK;
    const float* Bp = Bm + (size_t)bK * N + bn + bCol;

    float acc[8][8];
    #pragma unroll
    for (int i = 0; i < 8; i++)
        #pragma unroll
        for (int j = 0; j < 8; j++) acc[i][j] = 0.f;

    for (int k0 = 0; k0 < K; k0 += 8) {
        float4 av = *(const float4*)(Ap + k0);
        As[aK+0][aRow] = av.x; As[aK+1][aRow] = av.y;
        As[aK+2][aRow] = av.z; As[aK+3][aRow] = av.w;
        *(float4*)&Bs[bK][bCol] = *(const float4*)(Bp + (size_t)k0 * N);
        __syncthreads();
        #pragma unroll
        for (int kk = 0; kk < 8; kk++) {
            float a[8], b[8];
            *(float4*)&a[0] = *(const float4*)&As[kk][ty*8];
            *(float4*)&a[4] = *(const float4*)&As[kk][ty*8+4];
            *(float4*)&b[0] = *(const float4*)&Bs[kk][tx*8];
            *(float4*)&b[4] = *(const float4*)&Bs[kk][tx*8+4];
            #pragma unroll
            for (int i = 0; i < 8; i++)
                #pragma unroll
                for (int j = 0; j < 8; j++)
                    acc[i][j] = fmaf(a[i], b[j], acc[i][j]);
        }
        __syncthreads();
    }

    #pragma unroll
    for (int i = 0; i < 8; i++) {
        float* cp = C + (size_t)(bm + ty*8 + i) * N + bn + tx*8;
        float4 c0 = make_float4(acc[i][0], acc[i][1], acc[i][2], acc[i][3]);
        float4 c1 = make_float4(acc[i][4], acc[i][5], acc[i][6], acc[i][7]);
        *(float4*)cp = c0;
        *(float4*)(cp + 4) = c1;
    }
}

// ---------------------------------------------------------------------------
// RoPE: build cos/sin table in double (position_ids == arange(S) per batch).
// ---------------------------------------------------------------------------
__global__ void rope_table_kernel()
{
    int idx = blockIdx.x * blockDim.x + threadIdx.x;
    if (idx >= S_ * 64) return;
    int pos = idx >> 6, j = idx & 63;
    double invf = pow(10000.0, -(double)(2 * j) / 128.0);
    double ang = (double)pos * invf;
    g_tab[idx*2]     = (float)cos(ang);
    g_tab[idx*2 + 1] = (float)sin(ang);
}

// Apply RoPE in-place to g_q (NH heads) and g_k (NKV heads).
// Each thread handles one (row, head, j) pair: dims j and j+64.
__global__ void rope_apply_kernel()
{
    int idx = blockIdx.x * blockDim.x + threadIdx.x;
    const int NQ = M_ * NH_ * 64;   // 4,194,304
    const int NK = M_ * NKV_ * 64;  // 1,048,576
    if (idx < NQ) {
        int m = idx >> 10;            // / (NH*64)
        int rest = idx & 1023;
        int h = rest >> 6, j = rest & 63;
        int s = m & (S_ - 1);
        float c  = g_tab[(s*64 + j)*2];
        float sn = g_tab[(s*64 + j)*2 + 1];
        size_t base = (size_t)m * (NH_*HD_) + h*HD_;
        float x1 = g_q[base + j], x2 = g_q[base + j + 64];
        g_q[base + j]      = x1*c - x2*sn;
        g_q[base + j + 64] = x2*c + x1*sn;
    } else if (idx < NQ + NK) {
        int i2 = idx - NQ;
        int m = i2 >> 8;              // / (NKV*64)
        int rest = i2 & 255;
        int h = rest >> 6, j = rest & 63;
        int s = m & (S_ - 1);
        float c  = g_tab[(s*64 + j)*2];
        float sn = g_tab[(s*64 + j)*2 + 1];
        size_t base = (size_t)m * (NKV_*HD_) + h*HD_;
        float x1 = g_k[base + j], x2 = g_k[base + j + 64];
        g_k[base + j]      = x1*c - x2*sn;
        g_k[base + j + 64] = x2*c + x1*sn;
    }
}

// ---------------------------------------------------------------------------
// Flash attention (fp32, causal, GQA n_rep=4).
// Block: 512 threads, BQ=128 queries, key tiles of 64, HD=128.
// Dynamic smem layout (floats):
//   Qs[128][128]  Ks[64][132](pad)  Vs[64][128]  Ss[128][65](pad)  m/l/alpha[128]
// ---------------------------------------------------------------------------
#define ATTN_SMEM_FLOATS (128*128 + 64*132 + 64*128 + 128*65 + 3*128)
#define ATTN_SMEM_BYTES  (ATTN_SMEM_FLOATS * 4)

__global__ __launch_bounds__(512) void attn_kernel()
{
    extern __shared__ float sm[];
    float* Qs   = sm;                  // 16384
    float* Ks   = Qs + 128*128;        // 8448
    float* Vs   = Ks + 64*132;         // 8192
    float* Ss   = Vs + 64*128;         // 8320
    float* mrow = Ss + 128*65;
    float* lrow = mrow + 128;
    float* arow = lrow + 128;

    // heavy (late) q-tiles first to reduce tail imbalance
    int qt = (gridDim.x - 1) - blockIdx.x;
    int h  = blockIdx.y, b = blockIdx.z;
    int kvh = h >> 2;                   // n_rep = 4
    int t = threadIdx.x;

    const float* qg = g_q + (size_t)b*S_*(NH_*HD_)  + (size_t)h*HD_;
    const float* kg = g_k + (size_t)b*S_*(NKV_*HD_) + (size_t)kvh*HD_;
    const float* vg = g_v + (size_t)b*S_*(NKV_*HD_) + (size_t)kvh*HD_;
    int qbase = qt * 128;

    // Load Q tile [128 x 128]
    for (int i = t; i < 128*32; i += 512) {
        int r = i >> 5, d4 = (i & 31) * 4;
        *(float4*)&Qs[r*128 + d4] =
            *(const float4*)&qg[(size_t)(qbase + r)*(NH_*HD_) + d4];
    }
    if (t < 128) { mrow[t] = -1e30f; lrow[t] = 0.f; }

    float o[4][8];
    #pragma unroll
    for (int i = 0; i < 4; i++)
        #pragma unroll
        for (int c = 0; c < 8; c++) o[i][c] = 0.f;

    const float scale = 0.08838834764831845f;  // 1/sqrt(128)
    int sr = (t >> 4) * 4;        // score rows (also PV rows)
    int sc = (t & 15) * 4;        // score cols
    int pc = (t & 15) * 8;        // PV/output cols

    int ntiles = 2*qt + 2;        // keys [0, qbase+128)
    for (int kt = 0; kt < ntiles; kt++) {
        __syncthreads();          // prev PV done before overwriting K/V
        int kbase = kt * 64;
        for (int i = t; i < 64*32; i += 512) {
            int r = i >> 5, d4 = (i & 31) * 4;
            *(float4*)&Ks[r*132 + d4] =
                *(const float4*)&kg[(size_t)(kbase + r)*(NKV_*HD_) + d4];
            *(float4*)&Vs[r*128 + d4] =
                *(const float4*)&vg[(size_t)(kbase + r)*(NKV_*HD_) + d4];
        }
        __syncthreads();

        // S[128x64] = Q @ K^T   (4x4 microtile, float4 along k)
        float s4[4][4];
        #pragma unroll
        for (int i = 0; i < 4; i++)
            #pragma unroll
            for (int j = 0; j < 4; j++) s4[i][j] = 0.f;
        for (int kk = 0; kk < 128; kk += 4) {
            float4 av[4], bv[4];
            #pragma unroll
            for (int i = 0; i < 4; i++) av[i] = *(const float4*)&Qs[(sr+i)*128 + kk];
            #pragma unroll
            for (int j = 0; j < 4; j++) bv[j] = *(const float4*)&Ks[(sc+j)*132 + kk];
            #pragma unroll
            for (int i = 0; i < 4; i++)
                #pragma unroll
                for (int j = 0; j < 4; j++)
                    s4[i][j] += av[i].x*bv[j].x + av[i].y*bv[j].y
                              + av[i].z*bv[j].z + av[i].w*bv[j].w;
        }
        bool maybe_mask = (kt >= 2*qt);  // only last two tiles touch diagonal
        #pragma unroll
        for (int i = 0; i < 4; i++)
            #pragma unroll
            for (int j = 0; j < 4; j++) {
                float val = s4[i][j] * scale;
                if (maybe_mask && (kbase + sc + j) > (qbase + sr + i)) val = -1e30f;
                Ss[(sr+i)*65 + sc + j] = val;
            }
        __syncthreads();

        // online softmax, one thread per query row
        if (t < 128) {
            float mold = mrow[t];
            float mx = mold;
            for (int j = 0; j < 64; j++) mx = fmaxf(mx, Ss[t*65 + j]);
            float al = expf(mold - mx);
            float sum = 0.f;
            for (int j = 0; j < 64; j++) {
                float p = expf(Ss[t*65 + j] - mx);
                Ss[t*65 + j] = p;
                sum += p;
            }
            lrow[t] = lrow[t]*al + sum;
            mrow[t] = mx;
            arow[t] = al;
        }
        __syncthreads();

        // rescale accumulators, then O += P @ V
        float al[4];
        #pragma unroll
        for (int i = 0; i < 4; i++) al[i] = arow[sr+i];
        #pragma unroll
        for (int i = 0; i < 4; i++)
            #pragma unroll
            for (int c = 0; c < 8; c++) o[i][c] *= al[i];

        for (int kj = 0; kj < 64; kj++) {
            float p[4];
            #pragma unroll
            for (int i = 0; i < 4; i++) p[i] = Ss[(sr+i)*65 + kj];
            float4 v0 = *(const float4*)&Vs[kj*128 + pc];
            float4 v1 = *(const float4*)&Vs[kj*128 + pc + 4];
            #pragma unroll
            for (int i = 0; i < 4; i++) {
                o[i][0] = fmaf(p[i], v0.x, o[i][0]);
                o[i][1] = fmaf(p[i], v0.y, o[i][1]);
                o[i][2] = fmaf(p[i], v0.z, o[i][2]);
                o[i][3] = fmaf(p[i], v0.w, o[i][3]);
                o[i][4] = fmaf(p[i], v1.x, o[i][4]);
                o[i][5] = fmaf(p[i], v1.y, o[i][5]);
                o[i][6] = fmaf(p[i], v1.z, o[i][6]);
                o[i][7] = fmaf(p[i], v1.w, o[i][7]);
            }
        }
    }

    // epilogue: divide by l, store to g_attn in (b,s,h,d) layout
    #pragma unroll
    for (int i = 0; i < 4; i++) {
        float inv = 1.0f / lrow[sr+i];
        size_t base = (size_t)((size_t)b*S_ + qbase + sr + i)*(NH_*HD_)
                    + (size_t)h*HD_ + pc;
        float4 r0 = make_float4(o[i][0]*inv, o[i][1]*inv, o[i][2]*inv, o[i][3]*inv);
        float4 r1 = make_float4(o[i][4]*inv, o[i][5]*inv, o[i][6]*inv, o[i][7]*inv);
        *(float4*)&g_attn[base]     = r0;
        *(float4*)&g_attn[base + 4] = r1;
    }
}

// ---------------------------------------------------------------------------
// Launch
// Inputs (metadata order): hidden_states f32, position_ids (== arange, unused),
//                          Wq, Wk, Wv, Wo f32.  Output: f32 [B,S,H].
// ---------------------------------------------------------------------------
extern "C" void kernel_launch(void* const* d_in, const int* in_sizes, int n_in,
                              void* d_out, int out_size)
{
    (void)in_sizes; (void)n_in; (void)out_size;
    const float* hs = (const float*)d_in[0];
    const float* Wq = (const float*)d_in[2];
    const float* Wk = (const float*)d_in[3];
    const float* Wv = (const float*)d_in[4];
    const float* Wo = (const float*)d_in[5];
    float* out = (float*)d_out;

    // QKV projections
    sgemm_kernel<<<dim3((NH_*HD_)/128,  M_/128), 256>>>(hs, Wq, nullptr, M_, NH_*HD_,  H_, 0, 1);
    sgemm_kernel<<<dim3((NKV_*HD_)/128, M_/128), 256>>>(hs, Wk, nullptr, M_, NKV_*HD_, H_, 0, 2);
    sgemm_kernel<<<dim3((NKV_*HD_)/128, M_/128), 256>>>(hs, Wv, nullptr, M_, NKV_*HD_, H_, 0, 3);

    // RoPE
    rope_table_kernel<<<(S_*64 + 255)/256, 256>>>();
    int nrope = M_*NH_*64 + M_*NKV_*64;
    rope_apply_kernel<<<(nrope + 255)/256, 256>>>();

    // Attention
    cudaFuncSetAttribute(attn_kernel,
                         cudaFuncAttributeMaxDynamicSharedMemorySize,
                         ATTN_SMEM_BYTES);
    attn_kernel<<<dim3(S_/128, NH_, B_), 512, ATTN_SMEM_BYTES>>>();

    // Output projection: g_attn @ Wo -> out
    sgemm_kernel<<<dim3(H_/128, M_/128), 256>>>(nullptr, Wo, out, M_, H_, NH_*HD_, 1, 0);
}

// round 7
// speedup vs baseline: 1.4886x; 1.4886x over previous
#include <cuda_runtime.h>
#include <cuda_bf16.h>
#include <stdint.h>
#include <math.h>

#define B_   2
#define S_   2048
#define H_   2048
#define NH_  16
#define NKV_ 4
#define HD_  128
#define M_   (B_*S_)

// ---------------- device scratch ----------------
__device__ __nv_bfloat16 hs_h[(size_t)M_*H_],      hs_l[(size_t)M_*H_];
__device__ __nv_bfloat16 wqt_h[(size_t)2048*2048], wqt_l[(size_t)2048*2048];
__device__ __nv_bfloat16 wkt_h[(size_t)512*2048],  wkt_l[(size_t)512*2048];
__device__ __nv_bfloat16 wvt_h[(size_t)512*2048],  wvt_l[(size_t)512*2048];
__device__ __nv_bfloat16 wot_h[(size_t)2048*2048], wot_l[(size_t)2048*2048];
__device__ __nv_bfloat16 g_ah[(size_t)M_*2048],    g_al[(size_t)M_*2048];
__device__ float g_q[(size_t)M_*2048];
__device__ float g_k[(size_t)M_*512];
__device__ float g_v[(size_t)M_*512];
__device__ float g_tab[(size_t)64*S_*2];   // [j][pos][cos,sin]

// ---------------- PTX helpers (sm_80+ only; no arch-suffix features) -------
__device__ __forceinline__ uint32_t smem_to_u32(const void* p) {
    uint32_t a;
    asm("{ .reg .u64 t; cvta.to.shared.u64 t, %1; cvt.u32.u64 %0, t; }"
        : "=r"(a) : "l"(p));
    return a;
}
__device__ __forceinline__ void ldsm_x4(uint32_t* r, uint32_t a) {
    asm volatile("ldmatrix.sync.aligned.m8n8.x4.shared.b16 {%0,%1,%2,%3}, [%4];"
        : "=r"(r[0]), "=r"(r[1]), "=r"(r[2]), "=r"(r[3]) : "r"(a));
}
__device__ __forceinline__ void ldsm_x2(uint32_t* r, uint32_t a) {
    asm volatile("ldmatrix.sync.aligned.m8n8.x2.shared.b16 {%0,%1}, [%2];"
        : "=r"(r[0]), "=r"(r[1]) : "r"(a));
}
__device__ __forceinline__ void mma_bf16(float* c, const uint32_t* a, const uint32_t* b) {
    asm volatile("mma.sync.aligned.m16n8k16.row.col.f32.bf16.bf16.f32 "
        "{%0,%1,%2,%3}, {%4,%5,%6,%7}, {%8,%9}, {%0,%1,%2,%3};"
        : "+f"(c[0]), "+f"(c[1]), "+f"(c[2]), "+f"(c[3])
        : "r"(a[0]), "r"(a[1]), "r"(a[2]), "r"(a[3]), "r"(b[0]), "r"(b[1]));
}
#define CP16(d, s)   asm volatile("cp.async.cg.shared.global [%0], [%1], 16;" :: "r"(d), "l"(s))
#define CP_COMMIT()  asm volatile("cp.async.commit_group;" ::: "memory")
#define CP_WAIT0()   asm volatile("cp.async.wait_group 0;" ::: "memory")
#define CP_WAIT1()   asm volatile("cp.async.wait_group 1;" ::: "memory")

// ---------------- prep kernels ----------------
__global__ void split_hs_kernel(const float* __restrict__ hs)
{
    const size_t n4 = (size_t)M_ * H_ / 4;
    for (size_t i = blockIdx.x * (size_t)blockDim.x + threadIdx.x; i < n4;
         i += (size_t)gridDim.x * blockDim.x) {
        float4 v = ((const float4*)hs)[i];
        float x[4] = {v.x, v.y, v.z, v.w};
        #pragma unroll
        for (int c = 0; c < 4; c++) {
            __nv_bfloat16 hi = __float2bfloat16(x[c]);
            hs_h[i*4 + c] = hi;
            hs_l[i*4 + c] = __float2bfloat16(x[c] - __bfloat162float(hi));
        }
    }
}

// W[K][N] row-major -> T_hi/T_lo[N][K] bf16
__global__ void wsplit_kernel(const float* __restrict__ W, int K, int N, int sel)
{
    __nv_bfloat16 *Th, *Tl;
    if (sel == 0)      { Th = wqt_h; Tl = wqt_l; }
    else if (sel == 1) { Th = wkt_h; Tl = wkt_l; }
    else if (sel == 2) { Th = wvt_h; Tl = wvt_l; }
    else               { Th = wot_h; Tl = wot_l; }
    __shared__ float ts[32][33];
    int n0 = blockIdx.x * 32, k0 = blockIdx.y * 32;
    int tx = threadIdx.x, ty = threadIdx.y;
    #pragma unroll
    for (int i = 0; i < 4; i++)
        ts[ty + i*8][tx] = W[(size_t)(k0 + ty + i*8) * N + n0 + tx];
    __syncthreads();
    #pragma unroll
    for (int i = 0; i < 4; i++) {
        float x = ts[tx][ty + i*8];
        __nv_bfloat16 hi = __float2bfloat16(x);
        size_t o = (size_t)(n0 + ty + i*8) * K + k0 + tx;
        Th[o] = hi;
        Tl[o] = __float2bfloat16(x - __bfloat162float(hi));
    }
}

__global__ void rope_table_kernel()
{
    int idx = blockIdx.x * blockDim.x + threadIdx.x;
    if (idx >= S_ * 64) return;
    int j = idx >> 11, pos = idx & (S_ - 1);
    double ang = (double)pos * pow(10000.0, -(double)(2 * j) / 128.0);
    g_tab[idx*2]     = (float)cos(ang);
    g_tab[idx*2 + 1] = (float)sin(ang);
}

// ---------------------------------------------------------------------------
// Split-bf16 GEMM on warp tensor cores (mma.sync m16n8k16, sm_80+ PTX).
// C[M,N] = A[M,K] @ W[K,N]: A = Ah+Al bf16 [M,K]; W^T = Bh+Bl bf16 [N,K].
// 3 passes AhBh + AhBl + AlBh, fp32 accum.
// CTA 128x128, BK=32, 8 warps, warp tile 64x32 (n-atoms split +-64 so RoPE
// pairs (j, j+64) live in the same warp/lane).  cp.async double buffer.
// ---------------------------------------------------------------------------
#define TPAD    40          // smem row stride (bf16 elems): 80B, conflict-free
#define TILEB   10240u      // one 128 x 32 bf16 tile (128*40*2)
#define BUFB    (4u*TILEB)  // Ah, Al, Bh, Bl
#define MM_SMEM (2u*BUFB)   // 81,920 B

__device__ __forceinline__ void compute_chunk(uint32_t tb, float (*acc)[4][4],
                                              int lane, int wm, int wn)
{
    #pragma unroll
    for (int ks = 0; ks < 2; ks++) {
        const int k0 = ks * 16;
        uint32_t ah[4][4], al[4][4], bh[4][2], bl[4][2];
        const int arow = wm*64 + (lane & 15);
        const int acol = k0 + (lane >> 4) * 8;
        #pragma unroll
        for (int ma = 0; ma < 4; ma++) {
            uint32_t off = (uint32_t)(((arow + ma*16)*TPAD + acol) * 2);
            ldsm_x4(ah[ma], tb + off);
            ldsm_x4(al[ma], tb + TILEB + off);
        }
        const int bl8 = lane & 15;
        #pragma unroll
        for (int na = 0; na < 4; na++) {
            int nc = wn*16 + (na&1)*8 + (na>>1)*64 + (bl8 & 7);
            uint32_t off = (uint32_t)((nc*TPAD + k0 + (bl8 >> 3)*8) * 2);
            ldsm_x2(bh[na], tb + 2*TILEB + off);
            ldsm_x2(bl[na], tb + 3*TILEB + off);
        }
        #pragma unroll
        for (int ma = 0; ma < 4; ma++)
            #pragma unroll
            for (int na = 0; na < 4; na++) {
                mma_bf16(acc[ma][na], ah[ma], bh[na]);
                mma_bf16(acc[ma][na], ah[ma], bl[na]);
                mma_bf16(acc[ma][na], al[ma], bh[na]);
            }
    }
}

__global__ __launch_bounds__(256) void mm_mma(
    float* __restrict__ Cout, int K, int asel, int bsel, int mode, int ncols)
{
    extern __shared__ char dsm[];
    const uint32_t sbase = smem_to_u32(dsm);
    const int t = threadIdx.x, lane = t & 31, wid = t >> 5;
    const int wm = wid >> 2, wn = wid & 3;
    const int bn = blockIdx.x * 128, bm = blockIdx.y * 128;

    const __nv_bfloat16 *Ah, *Al, *Bh, *Bl;
    if (asel == 0) { Ah = hs_h; Al = hs_l; } else { Ah = g_ah; Al = g_al; }
    if (bsel == 0)      { Bh = wqt_h; Bl = wqt_l; }
    else if (bsel == 1) { Bh = wkt_h; Bl = wkt_l; }
    else if (bsel == 2) { Bh = wvt_h; Bl = wvt_l; }
    else                { Bh = wot_h; Bl = wot_l; }

    float acc[4][4][4];
    #pragma unroll
    for (int a = 0; a < 4; a++)
        #pragma unroll
        for (int b = 0; b < 4; b++)
            #pragma unroll
            for (int c = 0; c < 4; c++) acc[a][b][c] = 0.f;

    const int NK = K >> 5;

#define LOADT(SRC, RB, TOFF) \
    _Pragma("unroll") \
    for (int i = 0; i < 2; i++) { \
        int idx = t + i*256; \
        int row = idx >> 2, cc = idx & 3; \
        uint32_t dst = sbase + buf + (TOFF) + (uint32_t)((row*TPAD + cc*8)*2); \
        const void* src = (SRC) + (size_t)((RB) + row)*K + k0 + cc*8; \
        CP16(dst, src); \
    }

    {   // prefetch chunk 0
        const int k0 = 0; const uint32_t buf = 0;
        LOADT(Ah, bm, 0) LOADT(Al, bm, TILEB)
        LOADT(Bh, bn, 2*TILEB) LOADT(Bl, bn, 3*TILEB)
        CP_COMMIT();
    }
    for (int kt = 0; kt < NK; kt++) {
        if (kt + 1 < NK) {
            const int k0 = (kt + 1) << 5;
            const uint32_t buf = (uint32_t)((kt + 1) & 1) * BUFB;
            LOADT(Ah, bm, 0) LOADT(Al, bm, TILEB)
            LOADT(Bh, bn, 2*TILEB) LOADT(Bl, bn, 3*TILEB)
            CP_COMMIT();
            CP_WAIT1();
        } else {
            CP_WAIT0();
        }
        __syncthreads();
        compute_chunk(sbase + (uint32_t)(kt & 1) * BUFB, acc, lane, wm, wn);
        __syncthreads();
    }
#undef LOADT

    // ---- epilogue ----
    float* dst;
    if (mode == 1)      dst = g_q;
    else if (mode == 2) dst = g_k;
    else if (mode == 3) dst = g_v;
    else                dst = Cout;

    #pragma unroll
    for (int ma = 0; ma < 4; ma++) {
        int r0 = bm + wm*64 + ma*16 + (lane >> 2);
        if (mode == 1 || mode == 2) {
            // RoPE: acc[.][na] (cols j in [0,64)) pairs with acc[.][na+2] (j+64)
            #pragma unroll
            for (int na = 0; na < 2; na++) {
                int jb = wn*16 + na*8 + 2*(lane & 3);
                #pragma unroll
                for (int half = 0; half < 2; half++) {
                    int r = r0 + half*8;
                    int spos = r & (S_ - 1);
                    float c0 = g_tab[((size_t)jb*S_ + spos)*2];
                    float s0 = g_tab[((size_t)jb*S_ + spos)*2 + 1];
                    float c1 = g_tab[((size_t)(jb+1)*S_ + spos)*2];
                    float s1 = g_tab[((size_t)(jb+1)*S_ + spos)*2 + 1];
                    float x1a = acc[ma][na][half*2+0], x1b = acc[ma][na][half*2+1];
                    float x2a = acc[ma][na+2][half*2+0], x2b = acc[ma][na+2][half*2+1];
                    float* p = dst + (size_t)r*ncols + bn + jb;
                    *(float2*)p        = make_float2(x1a*c0 - x2a*s0, x1b*c1 - x2b*s1);
                    *(float2*)(p + 64) = make_float2(x2a*c0 + x1a*s0, x2b*c1 + x1b*s1);
                }
            }
        } else {
            #pragma unroll
            for (int na = 0; na < 4; na++) {
                int col = bn + wn*16 + (na&1)*8 + (na>>1)*64 + 2*(lane & 3);
                float* p0 = dst + (size_t)r0*ncols + col;
                float* p1 = dst + (size_t)(r0+8)*ncols + col;
                *(float2*)p0 = make_float2(acc[ma][na][0], acc[ma][na][1]);
                *(float2*)p1 = make_float2(acc[ma][na][2], acc[ma][na][3]);
            }
        }
    }
}

// ---------------------------------------------------------------------------
// Flash attention (fp32, causal, GQA n_rep=4). Proven R2 core; epilogue emits
// bf16 hi/lo into g_ah/g_al for the tensor-core out-proj.
// ---------------------------------------------------------------------------
#define ATTN_SMEM_FLOATS (128*128 + 64*132 + 64*128 + 128*65 + 3*128)
#define ATTN_SMEM_BYTES  (ATTN_SMEM_FLOATS * 4)

__global__ __launch_bounds__(512) void attn_kernel()
{
    extern __shared__ float sm[];
    float* Qs   = sm;
    float* Ks   = Qs + 128*128;
    float* Vs   = Ks + 64*132;
    float* Ss   = Vs + 64*128;
    float* mrow = Ss + 128*65;
    float* lrow = mrow + 128;
    float* arow = lrow + 128;

    int qt = (gridDim.x - 1) - blockIdx.x;   // heavy q-tiles first
    int h  = blockIdx.y, b = blockIdx.z;
    int kvh = h >> 2;
    int t = threadIdx.x;

    const float* qg = g_q + (size_t)b*S_*2048 + h*128;
    const float* kg = g_k + (size_t)b*S_*512  + kvh*128;
    const float* vg = g_v + (size_t)b*S_*512  + kvh*128;
    int qbase = qt * 128;

    for (int i = t; i < 128*32; i += 512) {
        int r = i >> 5, d4 = (i & 31) * 4;
        *(float4*)&Qs[r*128 + d4] = *(const float4*)&qg[(size_t)(qbase + r)*2048 + d4];
    }
    if (t < 128) { mrow[t] = -1e30f; lrow[t] = 0.f; }

    float o[4][8];
    #pragma unroll
    for (int i = 0; i < 4; i++)
        #pragma unroll
        for (int c = 0; c < 8; c++) o[i][c] = 0.f;

    const float scale = 0.08838834764831845f;
    int sr = (t >> 4) * 4, sc = (t & 15) * 4, pc = (t & 15) * 8;

    int ntiles = 2*qt + 2;
    for (int kt = 0; kt < ntiles; kt++) {
        __syncthreads();
        int kbase = kt * 64;
        for (int i = t; i < 64*32; i += 512) {
            int r = i >> 5, d4 = (i & 31) * 4;
            *(float4*)&Ks[r*132 + d4] = *(const float4*)&kg[(size_t)(kbase + r)*512 + d4];
            *(float4*)&Vs[r*128 + d4] = *(const float4*)&vg[(size_t)(kbase + r)*512 + d4];
        }
        __syncthreads();

        float s4[4][4];
        #pragma unroll
        for (int i = 0; i < 4; i++)
            #pragma unroll
            for (int j = 0; j < 4; j++) s4[i][j] = 0.f;
        for (int kk = 0; kk < 128; kk += 4) {
            float4 av[4], bv[4];
            #pragma unroll
            for (int i = 0; i < 4; i++) av[i] = *(const float4*)&Qs[(sr+i)*128 + kk];
            #pragma unroll
            for (int j = 0; j < 4; j++) bv[j] = *(const float4*)&Ks[(sc+j)*132 + kk];
            #pragma unroll
            for (int i = 0; i < 4; i++)
                #pragma unroll
                for (int j = 0; j < 4; j++)
                    s4[i][j] += av[i].x*bv[j].x + av[i].y*bv[j].y
                              + av[i].z*bv[j].z + av[i].w*bv[j].w;
        }
        bool maybe_mask = (kt >= 2*qt);
        #pragma unroll
        for (int i = 0; i < 4; i++)
            #pragma unroll
            for (int j = 0; j < 4; j++) {
                float val = s4[i][j] * scale;
                if (maybe_mask && (kbase + sc + j) > (qbase + sr + i)) val = -1e30f;
                Ss[(sr+i)*65 + sc + j] = val;
            }
        __syncthreads();

        if (t < 128) {
            float mold = mrow[t];
            float mx = mold;
            for (int j = 0; j < 64; j++) mx = fmaxf(mx, Ss[t*65 + j]);
            float al = expf(mold - mx);
            float sum = 0.f;
            for (int j = 0; j < 64; j++) {
                float p = expf(Ss[t*65 + j] - mx);
                Ss[t*65 + j] = p;
                sum += p;
            }
            lrow[t] = lrow[t]*al + sum;
            mrow[t] = mx;
            arow[t] = al;
        }
        __syncthreads();

        float al[4];
        #pragma unroll
        for (int i = 0; i < 4; i++) al[i] = arow[sr+i];
        #pragma unroll
        for (int i = 0; i < 4; i++)
            #pragma unroll
            for (int c = 0; c < 8; c++) o[i][c] *= al[i];

        for (int kj = 0; kj < 64; kj++) {
            float p[4];
            #pragma unroll
            for (int i = 0; i < 4; i++) p[i] = Ss[(sr+i)*65 + kj];
            float4 v0 = *(const float4*)&Vs[kj*128 + pc];
            float4 v1 = *(const float4*)&Vs[kj*128 + pc + 4];
            #pragma unroll
            for (int i = 0; i < 4; i++) {
                o[i][0] = fmaf(p[i], v0.x, o[i][0]);
                o[i][1] = fmaf(p[i], v0.y, o[i][1]);
                o[i][2] = fmaf(p[i], v0.z, o[i][2]);
                o[i][3] = fmaf(p[i], v0.w, o[i][3]);
                o[i][4] = fmaf(p[i], v1.x, o[i][4]);
                o[i][5] = fmaf(p[i], v1.y, o[i][5]);
                o[i][6] = fmaf(p[i], v1.z, o[i][6]);
                o[i][7] = fmaf(p[i], v1.w, o[i][7]);
            }
        }
    }

    // epilogue: divide by l, emit bf16 hi/lo in (b,s,h*128+d) layout
    #pragma unroll
    for (int i = 0; i < 4; i++) {
        float inv = 1.0f / lrow[sr+i];
        size_t base = (size_t)((size_t)b*S_ + qbase + sr + i)*2048 + (size_t)h*128 + pc;
        __nv_bfloat16 hb[8], lb[8];
        #pragma unroll
        for (int c = 0; c < 8; c++) {
            float x = o[i][c] * inv;
            __nv_bfloat16 hi = __float2bfloat16(x);
            hb[c] = hi;
            lb[c] = __float2bfloat16(x - __bfloat162float(hi));
        }
        *(uint4*)&g_ah[base] = *(uint4*)hb;
        *(uint4*)&g_al[base] = *(uint4*)lb;
    }
}

// ---------------------------------------------------------------------------
// Launch.  Inputs: hidden_states f32, position_ids (arange, unused),
//                  Wq, Wk, Wv, Wo f32.  Output f32 [B,S,H].
// ---------------------------------------------------------------------------
extern "C" void kernel_launch(void* const* d_in, const int* in_sizes, int n_in,
                              void* d_out, int out_size)
{
    (void)in_sizes; (void)n_in; (void)out_size;
    const float* hs = (const float*)d_in[0];
    const float* Wq = (const float*)d_in[2];
    const float* Wk = (const float*)d_in[3];
    const float* Wv = (const float*)d_in[4];
    const float* Wo = (const float*)d_in[5];
    float* out = (float*)d_out;

    cudaFuncSetAttribute(mm_mma, cudaFuncAttributeMaxDynamicSharedMemorySize, MM_SMEM);
    cudaFuncSetAttribute(attn_kernel, cudaFuncAttributeMaxDynamicSharedMemorySize, ATTN_SMEM_BYTES);

    // prep: hi/lo splits + weight transposes + rope table
    split_hs_kernel<<<1024, 256>>>(hs);
    wsplit_kernel<<<dim3(2048/32, 2048/32), dim3(32, 8)>>>(Wq, 2048, 2048, 0);
    wsplit_kernel<<<dim3(512/32,  2048/32), dim3(32, 8)>>>(Wk, 2048, 512,  1);
    wsplit_kernel<<<dim3(512/32,  2048/32), dim3(32, 8)>>>(Wv, 2048, 512,  2);
    wsplit_kernel<<<dim3(2048/32, 2048/32), dim3(32, 8)>>>(Wo, 2048, 2048, 3);
    rope_table_kernel<<<(S_*64 + 255)/256, 256>>>();

    // projections on tensor cores, RoPE fused for Q/K
    mm_mma<<<dim3(16, 32), 256, MM_SMEM>>>(nullptr, 2048, 0, 0, 1, 2048);
    mm_mma<<<dim3(4,  32), 256, MM_SMEM>>>(nullptr, 2048, 0, 1, 2, 512);
    mm_mma<<<dim3(4,  32), 256, MM_SMEM>>>(nullptr, 2048, 0, 2, 3, 512);

    // attention
    attn_kernel<<<dim3(S_/128, NH_, B_), 512, ATTN_SMEM_BYTES>>>();

    // output projection
    mm_mma<<<dim3(16, 32), 256, MM_SMEM>>>(out, 2048, 1, 3, 0, 2048);
}

// round 10
// speedup vs baseline: 3.5639x; 2.3941x over previous
#include <cuda_runtime.h>
#include <cuda_bf16.h>
#include <stdint.h>
#include <math.h>

#define B_   2
#define S_   2048
#define H_   2048
#define NH_  16
#define NKV_ 4
#define HD_  128
#define M_   (B_*S_)
#define LOG2E 1.4426950408889634f

// ---------------- device scratch ----------------
__device__ __nv_bfloat16 hs_h[(size_t)M_*H_],      hs_l[(size_t)M_*H_];
__device__ __nv_bfloat16 wqt_h[(size_t)2048*2048], wqt_l[(size_t)2048*2048];
__device__ __nv_bfloat16 wkt_h[(size_t)512*2048],  wkt_l[(size_t)512*2048];
__device__ __nv_bfloat16 wvt_h[(size_t)512*2048],  wvt_l[(size_t)512*2048];
__device__ __nv_bfloat16 wot_h[(size_t)2048*2048], wot_l[(size_t)2048*2048];
__device__ __nv_bfloat16 g_ah[(size_t)M_*2048],    g_al[(size_t)M_*2048];
__device__ __nv_bfloat16 g_qh[(size_t)M_*2048],    g_ql[(size_t)M_*2048];
__device__ __nv_bfloat16 g_kh[(size_t)M_*512],     g_kl[(size_t)M_*512];
__device__ __nv_bfloat16 g_vh[(size_t)M_*512],     g_vl[(size_t)M_*512];
__device__ float g_tab[(size_t)64*S_*2];   // [j][pos][cos,sin]

// ---------------- PTX helpers (sm_80+ only) ----------------
__device__ __forceinline__ uint32_t smem_to_u32(const void* p) {
    uint32_t a;
    asm("{ .reg .u64 t; cvta.to.shared.u64 t, %1; cvt.u32.u64 %0, t; }"
        : "=r"(a) : "l"(p));
    return a;
}
__device__ __forceinline__ void ldsm_x4(uint32_t* r, uint32_t a) {
    asm volatile("ldmatrix.sync.aligned.m8n8.x4.shared.b16 {%0,%1,%2,%3}, [%4];"
        : "=r"(r[0]), "=r"(r[1]), "=r"(r[2]), "=r"(r[3]) : "r"(a));
}
__device__ __forceinline__ void ldsm_x2(uint32_t* r, uint32_t a) {
    asm volatile("ldmatrix.sync.aligned.m8n8.x2.shared.b16 {%0,%1}, [%2];"
        : "=r"(r[0]), "=r"(r[1]) : "r"(a));
}
__device__ __forceinline__ void ldsm_x2_t(uint32_t* r, uint32_t a) {
    asm volatile("ldmatrix.sync.aligned.m8n8.x2.trans.shared.b16 {%0,%1}, [%2];"
        : "=r"(r[0]), "=r"(r[1]) : "r"(a));
}
__device__ __forceinline__ void mma_bf16(float* c, const uint32_t* a, const uint32_t* b) {
    asm volatile("mma.sync.aligned.m16n8k16.row.col.f32.bf16.bf16.f32 "
        "{%0,%1,%2,%3}, {%4,%5,%6,%7}, {%8,%9}, {%0,%1,%2,%3};"
        : "+f"(c[0]), "+f"(c[1]), "+f"(c[2]), "+f"(c[3])
        : "r"(a[0]), "r"(a[1]), "r"(a[2]), "r"(a[3]), "r"(b[0]), "r"(b[1]));
}
#define CP16(d, s)   asm volatile("cp.async.cg.shared.global [%0], [%1], 16;" :: "r"(d), "l"(s))
#define CP_COMMIT()  asm volatile("cp.async.commit_group;" ::: "memory")
#define CP_WAIT0()   asm volatile("cp.async.wait_group 0;" ::: "memory")
#define CP_WAIT1()   asm volatile("cp.async.wait_group 1;" ::: "memory")

__device__ __forceinline__ uint32_t pack_bf16(float a, float b) {
    uint32_t lo = (uint32_t)__bfloat16_as_ushort(__float2bfloat16(a));
    uint32_t hi = (uint32_t)__bfloat16_as_ushort(__float2bfloat16(b));
    return lo | (hi << 16);
}
// split (a,b) into packed bf16 hi-pair and lo-pair
__device__ __forceinline__ void split2(float a, float b, uint32_t& h, uint32_t& l) {
    __nv_bfloat16 ah = __float2bfloat16(a), bh = __float2bfloat16(b);
    h = (uint32_t)__bfloat16_as_ushort(ah) | ((uint32_t)__bfloat16_as_ushort(bh) << 16);
    l = pack_bf16(a - __bfloat162float(ah), b - __bfloat162float(bh));
}
// 2^t for t <= 0 (clamped at -126), branch-free FMA-only
__device__ __forceinline__ float fexp2(float t) {
    t = fmaxf(t, -126.0f);
    float fi = floorf(t);
    float f = t - fi;
    float p =            1.5252734e-05f;
    p = fmaf(p, f, 1.5403530e-04f);
    p = fmaf(p, f, 1.3333558e-03f);
    p = fmaf(p, f, 9.6181291e-03f);
    p = fmaf(p, f, 5.5504109e-02f);
    p = fmaf(p, f, 2.4022651e-01f);
    p = fmaf(p, f, 6.9314718e-01f);
    p = fmaf(p, f, 1.0f);
    return __int_as_float(__float_as_int(p) + (__float2int_rn(fi) << 23));
}

// ---------------- prep kernels ----------------
__global__ void split_hs_kernel(const float* __restrict__ hs)
{
    const size_t n4 = (size_t)M_ * H_ / 4;
    for (size_t i = blockIdx.x * (size_t)blockDim.x + threadIdx.x; i < n4;
         i += (size_t)gridDim.x * blockDim.x) {
        float4 v = ((const float4*)hs)[i];
        float x[4] = {v.x, v.y, v.z, v.w};
        #pragma unroll
        for (int c = 0; c < 4; c++) {
            __nv_bfloat16 hi = __float2bfloat16(x[c]);
            hs_h[i*4 + c] = hi;
            hs_l[i*4 + c] = __float2bfloat16(x[c] - __bfloat162float(hi));
        }
    }
}

// W[K][N] row-major -> T_hi/T_lo[N][K] bf16
__global__ void wsplit_kernel(const float* __restrict__ W, int K, int N, int sel)
{
    __nv_bfloat16 *Th, *Tl;
    if (sel == 0)      { Th = wqt_h; Tl = wqt_l; }
    else if (sel == 1) { Th = wkt_h; Tl = wkt_l; }
    else if (sel == 2) { Th = wvt_h; Tl = wvt_l; }
    else               { Th = wot_h; Tl = wot_l; }
    __shared__ float ts[32][33];
    int n0 = blockIdx.x * 32, k0 = blockIdx.y * 32;
    int tx = threadIdx.x, ty = threadIdx.y;
    #pragma unroll
    for (int i = 0; i < 4; i++)
        ts[ty + i*8][tx] = W[(size_t)(k0 + ty + i*8) * N + n0 + tx];
    __syncthreads();
    #pragma unroll
    for (int i = 0; i < 4; i++) {
        float x = ts[tx][ty + i*8];
        __nv_bfloat16 hi = __float2bfloat16(x);
        size_t o = (size_t)(n0 + ty + i*8) * K + k0 + tx;
        Th[o] = hi;
        Tl[o] = __float2bfloat16(x - __bfloat162float(hi));
    }
}

__global__ void rope_table_kernel()
{
    int idx = blockIdx.x * blockDim.x + threadIdx.x;
    if (idx >= S_ * 64) return;
    int j = idx >> 11, pos = idx & (S_ - 1);
    double ang = (double)pos * pow(10000.0, -(double)(2 * j) / 128.0);
    g_tab[idx*2]     = (float)cos(ang);
    g_tab[idx*2 + 1] = (float)sin(ang);
}

// ---------------------------------------------------------------------------
// Split-bf16 GEMM (mma.sync m16n8k16). C = A @ W; 3 passes AhBh+AhBl+AlBh.
// CTA 128x128, BK=32, 8 warps 64x32, cp.async double buffer.
// mode: 0 -> f32 Cout, 1 rope->g_qh/l, 2 rope->g_kh/l, 3 -> g_vh/l.
// ---------------------------------------------------------------------------
#define TPAD    40
#define TILEB   10240u
#define BUFB    (4u*TILEB)
#define MM_SMEM (2u*BUFB)   // 81,920 B

__device__ __forceinline__ void compute_chunk(uint32_t tb, float (*acc)[4][4],
                                              int lane, int wm, int wn)
{
    #pragma unroll
    for (int ks = 0; ks < 2; ks++) {
        const int k0 = ks * 16;
        uint32_t ah[4][4], al[4][4], bh[4][2], bl[4][2];
        const int arow = wm*64 + (lane & 15);
        const int acol = k0 + (lane >> 4) * 8;
        #pragma unroll
        for (int ma = 0; ma < 4; ma++) {
            uint32_t off = (uint32_t)(((arow + ma*16)*TPAD + acol) * 2);
            ldsm_x4(ah[ma], tb + off);
            ldsm_x4(al[ma], tb + TILEB + off);
        }
        const int bl8 = lane & 15;
        #pragma unroll
        for (int na = 0; na < 4; na++) {
            int nc = wn*16 + (na&1)*8 + (na>>1)*64 + (bl8 & 7);
            uint32_t off = (uint32_t)((nc*TPAD + k0 + (bl8 >> 3)*8) * 2);
            ldsm_x2(bh[na], tb + 2*TILEB + off);
            ldsm_x2(bl[na], tb + 3*TILEB + off);
        }
        #pragma unroll
        for (int ma = 0; ma < 4; ma++)
            #pragma unroll
            for (int na = 0; na < 4; na++) {
                mma_bf16(acc[ma][na], ah[ma], bh[na]);
                mma_bf16(acc[ma][na], ah[ma], bl[na]);
                mma_bf16(acc[ma][na], al[ma], bh[na]);
            }
    }
}

__global__ __launch_bounds__(256) void mm_mma(
    float* __restrict__ Cout, int K, int asel, int bsel, int mode, int ncols)
{
    extern __shared__ char dsm[];
    const uint32_t sbase = smem_to_u32(dsm);
    const int t = threadIdx.x, lane = t & 31, wid = t >> 5;
    const int wm = wid >> 2, wn = wid & 3;
    const int bn = blockIdx.x * 128, bm = blockIdx.y * 128;

    const __nv_bfloat16 *Ah, *Al, *Bh, *Bl;
    if (asel == 0) { Ah = hs_h; Al = hs_l; } else { Ah = g_ah; Al = g_al; }
    if (bsel == 0)      { Bh = wqt_h; Bl = wqt_l; }
    else if (bsel == 1) { Bh = wkt_h; Bl = wkt_l; }
    else if (bsel == 2) { Bh = wvt_h; Bl = wvt_l; }
    else                { Bh = wot_h; Bl = wot_l; }

    float acc[4][4][4];
    #pragma unroll
    for (int a = 0; a < 4; a++)
        #pragma unroll
        for (int b = 0; b < 4; b++)
            #pragma unroll
            for (int c = 0; c < 4; c++) acc[a][b][c] = 0.f;

    const int NK = K >> 5;

#define LOADT(SRC, RB, TOFF) \
    _Pragma("unroll") \
    for (int i = 0; i < 2; i++) { \
        int idx = t + i*256; \
        int row = idx >> 2, cc = idx & 3; \
        uint32_t dst = sbase + buf + (TOFF) + (uint32_t)((row*TPAD + cc*8)*2); \
        const void* src = (SRC) + (size_t)((RB) + row)*K + k0 + cc*8; \
        CP16(dst, src); \
    }

    {
        const int k0 = 0; const uint32_t buf = 0;
        LOADT(Ah, bm, 0) LOADT(Al, bm, TILEB)
        LOADT(Bh, bn, 2*TILEB) LOADT(Bl, bn, 3*TILEB)
        CP_COMMIT();
    }
    for (int kt = 0; kt < NK; kt++) {
        if (kt + 1 < NK) {
            const int k0 = (kt + 1) << 5;
            const uint32_t buf = (uint32_t)((kt + 1) & 1) * BUFB;
            LOADT(Ah, bm, 0) LOADT(Al, bm, TILEB)
            LOADT(Bh, bn, 2*TILEB) LOADT(Bl, bn, 3*TILEB)
            CP_COMMIT();
            CP_WAIT1();
        } else {
            CP_WAIT0();
        }
        __syncthreads();
        compute_chunk(sbase + (uint32_t)(kt & 1) * BUFB, acc, lane, wm, wn);
        __syncthreads();
    }
#undef LOADT

    // ---- epilogue ----
    if (mode == 0) {
        #pragma unroll
        for (int ma = 0; ma < 4; ma++) {
            int r0 = bm + wm*64 + ma*16 + (lane >> 2);
            #pragma unroll
            for (int na = 0; na < 4; na++) {
                int col = bn + wn*16 + (na&1)*8 + (na>>1)*64 + 2*(lane & 3);
                *(float2*)(Cout + (size_t)r0*ncols + col)     = make_float2(acc[ma][na][0], acc[ma][na][1]);
                *(float2*)(Cout + (size_t)(r0+8)*ncols + col) = make_float2(acc[ma][na][2], acc[ma][na][3]);
            }
        }
    } else if (mode == 3) {
        #pragma unroll
        for (int ma = 0; ma < 4; ma++) {
            int r0 = bm + wm*64 + ma*16 + (lane >> 2);
            #pragma unroll
            for (int na = 0; na < 4; na++) {
                int col = bn + wn*16 + (na&1)*8 + (na>>1)*64 + 2*(lane & 3);
                uint32_t h0, l0, h1, l1;
                split2(acc[ma][na][0], acc[ma][na][1], h0, l0);
                split2(acc[ma][na][2], acc[ma][na][3], h1, l1);
                *(uint32_t*)&g_vh[(size_t)r0*ncols + col]     = h0;
                *(uint32_t*)&g_vl[(size_t)r0*ncols + col]     = l0;
                *(uint32_t*)&g_vh[(size_t)(r0+8)*ncols + col] = h1;
                *(uint32_t*)&g_vl[(size_t)(r0+8)*ncols + col] = l1;
            }
        }
    } else {
        __nv_bfloat16* dh = (mode == 1) ? g_qh : g_kh;
        __nv_bfloat16* dl = (mode == 1) ? g_ql : g_kl;
        #pragma unroll
        for (int ma = 0; ma < 4; ma++) {
            int r0 = bm + wm*64 + ma*16 + (lane >> 2);
            #pragma unroll
            for (int na = 0; na < 2; na++) {
                int jb = wn*16 + na*8 + 2*(lane & 3);
                #pragma unroll
                for (int half = 0; half < 2; half++) {
                    int r = r0 + half*8;
                    int spos = r & (S_ - 1);
                    float c0 = g_tab[((size_t)jb*S_ + spos)*2];
                    float s0 = g_tab[((size_t)jb*S_ + spos)*2 + 1];
                    float c1 = g_tab[((size_t)(jb+1)*S_ + spos)*2];
                    float s1 = g_tab[((size_t)(jb+1)*S_ + spos)*2 + 1];
                    float x1a = acc[ma][na][half*2+0],   x1b = acc[ma][na][half*2+1];
                    float x2a = acc[ma][na+2][half*2+0], x2b = acc[ma][na+2][half*2+1];
                    float y0 = x1a*c0 - x2a*s0, y1 = x1b*c1 - x2b*s1;   // cols jb, jb+1
                    float z0 = x2a*c0 + x1a*s0, z1 = x2b*c1 + x1b*s1;   // cols jb+64, jb+65
                    uint32_t h0, l0, h1, l1;
                    split2(y0, y1, h0, l0);
                    split2(z0, z1, h1, l1);
                    size_t p = (size_t)r*ncols + bn + jb;
                    *(uint32_t*)&dh[p]      = h0;
                    *(uint32_t*)&dl[p]      = l0;
                    *(uint32_t*)&dh[p + 64] = h1;
                    *(uint32_t*)&dl[p + 64] = l1;
                }
            }
        }
    }
}

// ---------------------------------------------------------------------------
// Flash attention on mma.sync, split-bf16 both GEMMs, register softmax.
// 256 threads / 8 warps; warp w owns query rows [w*16, w*16+16).
// ---------------------------------------------------------------------------
#define QSTR 136
#define PSTR 72
#define QH_OFF 0u
#define QL_OFF 34816u
#define KH_OFF 69632u
#define KL_OFF 87040u
#define VH_OFF 104448u
#define VL_OFF 121856u
#define PH_OFF 139264u
#define PL_OFF 157696u
#define ATT_SMEM 176128u

__global__ __launch_bounds__(256) void attn_mma()
{
    extern __shared__ char dsm[];
    const uint32_t sb = smem_to_u32(dsm);
    const int t = threadIdx.x, lane = t & 31, wid = t >> 5;
    const int qt = 15 - blockIdx.x;          // heavy q-tiles first
    const int h = blockIdx.y, b = blockIdx.z;
    const int kvh = h >> 2;
    const int qbase = qt * 128;
    const int r_in = lane >> 2;              // 0..7
    const int c2 = (lane & 3) * 2;

    // load Q tile (hi+lo)
    {
        const __nv_bfloat16* qh = g_qh + (size_t)(b*S_ + qbase)*2048 + h*128;
        const __nv_bfloat16* ql = g_ql + (size_t)(b*S_ + qbase)*2048 + h*128;
        for (int i = t; i < 2048; i += 256) {
            int r = i >> 4, c = (i & 15) * 8;
            uint32_t d = sb + QH_OFF + (uint32_t)((r*QSTR + c)*2);
            CP16(d, qh + (size_t)r*2048 + c);
            CP16(d + QL_OFF, ql + (size_t)r*2048 + c);
        }
        CP_COMMIT();
    }

    float o[16][4];
    #pragma unroll
    for (int i = 0; i < 16; i++)
        #pragma unroll
        for (int e = 0; e < 4; e++) o[i][e] = 0.f;
    float m_run[2] = {-1e30f, -1e30f}, l_run[2] = {0.f, 0.f};

    const float scale = 0.08838834764831845f;
    const int ntiles = 2*qt + 2;
    for (int kt = 0; kt < ntiles; kt++) {
        const int kbase = kt * 64;
        __syncthreads();   // all warps done reading prev K/V
        for (int i = t; i < 1024; i += 256) {
            int r = i >> 4, c = (i & 15) * 8;
            uint32_t doff = (uint32_t)((r*QSTR + c)*2);
            size_t goff = (size_t)(b*S_ + kbase + r)*512 + kvh*128 + c;
            CP16(sb + KH_OFF + doff, g_kh + goff);
            CP16(sb + KL_OFF + doff, g_kl + goff);
            CP16(sb + VH_OFF + doff, g_vh + goff);
            CP16(sb + VL_OFF + doff, g_vl + goff);
        }
        CP_COMMIT();
        CP_WAIT0();
        __syncthreads();

        // ---- S = Q K^T (3-pass split) ----
        float s[8][4];
        #pragma unroll
        for (int na = 0; na < 8; na++)
            #pragma unroll
            for (int e = 0; e < 4; e++) s[na][e] = 0.f;
        #pragma unroll
        for (int ks = 0; ks < 8; ks++) {
            const int k0 = ks * 16;
            uint32_t ah[4], al[4];
            uint32_t aoff = sb + QH_OFF +
                (uint32_t)(((wid*16 + (lane & 15))*QSTR + k0 + (lane >> 4)*8)*2);
            ldsm_x4(ah, aoff);
            ldsm_x4(al, aoff + (QL_OFF - QH_OFF));
            #pragma unroll
            for (int na = 0; na < 8; na++) {
                uint32_t bh[2], bl[2];
                uint32_t boff = sb + KH_OFF +
                    (uint32_t)(((na*8 + (lane & 7))*QSTR + k0 + ((lane >> 3) & 1)*8)*2);
                ldsm_x2(bh, boff);
                ldsm_x2(bl, boff + (KL_OFF - KH_OFF));
                mma_bf16(s[na], ah, bh);
                mma_bf16(s[na], ah, bl);
                mma_bf16(s[na], al, bh);
            }
        }
        // scale + causal mask
        const bool mm = (kt >= 2*qt);
        #pragma unroll
        for (int na = 0; na < 8; na++)
            #pragma unroll
            for (int e = 0; e < 4; e++) {
                float v = s[na][e] * scale;
                if (mm) {
                    int col = kbase + na*8 + c2 + (e & 1);
                    int row = qbase + wid*16 + r_in + (e >> 1)*8;
                    if (col > row) v = -1e30f;
                }
                s[na][e] = v;
            }
        // row max (2 rows per lane)
        float mt[2] = {-1e30f, -1e30f};
        #pragma unroll
        for (int na = 0; na < 8; na++) {
            mt[0] = fmaxf(mt[0], fmaxf(s[na][0], s[na][1]));
            mt[1] = fmaxf(mt[1], fmaxf(s[na][2], s[na][3]));
        }
        #pragma unroll
        for (int x = 1; x < 4; x <<= 1) {
            mt[0] = fmaxf(mt[0], __shfl_xor_sync(0xFFFFFFFFu, mt[0], x));
            mt[1] = fmaxf(mt[1], __shfl_xor_sync(0xFFFFFFFFu, mt[1], x));
        }
        float mn0 = fmaxf(m_run[0], mt[0]), mn1 = fmaxf(m_run[1], mt[1]);
        float al0 = fexp2((m_run[0] - mn0) * LOG2E);
        float al1 = fexp2((m_run[1] - mn1) * LOG2E);
        m_run[0] = mn0; m_run[1] = mn1;

        // p = exp(s - m), row sums, store P (hi/lo) to this warp's smem rows
        float rs0 = 0.f, rs1 = 0.f;
        uint32_t pbase = sb + PH_OFF +
            (uint32_t)(((wid*16 + r_in)*PSTR + c2)*2);
        #pragma unroll
        for (int na = 0; na < 8; na++) {
            float p0 = fexp2((s[na][0] - mn0) * LOG2E);
            float p1 = fexp2((s[na][1] - mn0) * LOG2E);
            float p2 = fexp2((s[na][2] - mn1) * LOG2E);
            float p3 = fexp2((s[na][3] - mn1) * LOG2E);
            rs0 += p0 + p1; rs1 += p2 + p3;
            uint32_t h0, l0, h1, l1;
            split2(p0, p1, h0, l0);
            split2(p2, p3, h1, l1);
            uint32_t a0 = pbase + (uint32_t)(na*8*2);
            uint32_t a1 = a0 + (uint32_t)(8*PSTR*2);
            *(uint32_t*)(dsm + (a0 - sb))                    = h0;
            *(uint32_t*)(dsm + (a0 - sb) + (PL_OFF - PH_OFF)) = l0;
            *(uint32_t*)(dsm + (a1 - sb))                    = h1;
            *(uint32_t*)(dsm + (a1 - sb) + (PL_OFF - PH_OFF)) = l1;
        }
        #pragma unroll
        for (int x = 1; x < 4; x <<= 1) {
            rs0 += __shfl_xor_sync(0xFFFFFFFFu, rs0, x);
            rs1 += __shfl_xor_sync(0xFFFFFFFFu, rs1, x);
        }
        l_run[0] = l_run[0]*al0 + rs0;
        l_run[1] = l_run[1]*al1 + rs1;
        // rescale O
        #pragma unroll
        for (int nd = 0; nd < 16; nd++) {
            o[nd][0] *= al0; o[nd][1] *= al0;
            o[nd][2] *= al1; o[nd][3] *= al1;
        }
        __syncwarp();

        // ---- O += P V (3-pass split), V fragments via ldmatrix.trans ----
        #pragma unroll
        for (int kk = 0; kk < 4; kk++) {
            const int k0 = kk * 16;
            uint32_t ph4[4], pl4[4];
            uint32_t poff = sb + PH_OFF +
                (uint32_t)(((wid*16 + (lane & 15))*PSTR + k0 + (lane >> 4)*8)*2);
            ldsm_x4(ph4, poff);
            ldsm_x4(pl4, poff + (PL_OFF - PH_OFF));
            #pragma unroll
            for (int nd = 0; nd < 16; nd++) {
                uint32_t bh[2], bl[2];
                uint32_t voff = sb + VH_OFF +
                    (uint32_t)(((k0 + (lane & 15))*QSTR + nd*8)*2);
                ldsm_x2_t(bh, voff);
                ldsm_x2_t(bl, voff + (VL_OFF - VH_OFF));
                mma_bf16(o[nd], ph4, bh);
                mma_bf16(o[nd], pl4, bh);
                mma_bf16(o[nd], ph4, bl);
            }
        }
    }

    // ---- epilogue: /= l, emit bf16 hi/lo for out-proj ----
    float inv0 = 1.f / l_run[0], inv1 = 1.f / l_run[1];
    int row0 = b*S_ + qbase + wid*16 + r_in;
    #pragma unroll
    for (int nd = 0; nd < 16; nd++) {
        int d = nd*8 + c2;
        uint32_t h0, l0, h1, l1;
        split2(o[nd][0]*inv0, o[nd][1]*inv0, h0, l0);
        split2(o[nd][2]*inv1, o[nd][3]*inv1, h1, l1);
        size_t p0 = (size_t)row0*2048 + h*128 + d;
        size_t p1 = p0 + (size_t)8*2048;
        *(uint32_t*)&g_ah[p0] = h0;
        *(uint32_t*)&g_al[p0] = l0;
        *(uint32_t*)&g_ah[p1] = h1;
        *(uint32_t*)&g_al[p1] = l1;
    }
}

// ---------------------------------------------------------------------------
// Launch.  Inputs: hidden_states f32, position_ids (arange, unused),
//                  Wq, Wk, Wv, Wo f32.  Output f32 [B,S,H].
// ---------------------------------------------------------------------------
extern "C" void kernel_launch(void* const* d_in, const int* in_sizes, int n_in,
                              void* d_out, int out_size)
{
    (void)in_sizes; (void)n_in; (void)out_size;
    const float* hs = (const float*)d_in[0];
    const float* Wq = (const float*)d_in[2];
    const float* Wk = (const float*)d_in[3];
    const float* Wv = (const float*)d_in[4];
    const float* Wo = (const float*)d_in[5];
    float* out = (float*)d_out;

    cudaFuncSetAttribute(mm_mma, cudaFuncAttributeMaxDynamicSharedMemorySize, MM_SMEM);
    cudaFuncSetAttribute(attn_mma, cudaFuncAttributeMaxDynamicSharedMemorySize, ATT_SMEM);

    // prep
    split_hs_kernel<<<1024, 256>>>(hs);
    wsplit_kernel<<<dim3(2048/32, 2048/32), dim3(32, 8)>>>(Wq, 2048, 2048, 0);
    wsplit_kernel<<<dim3(512/32,  2048/32), dim3(32, 8)>>>(Wk, 2048, 512,  1);
    wsplit_kernel<<<dim3(512/32,  2048/32), dim3(32, 8)>>>(Wv, 2048, 512,  2);
    wsplit_kernel<<<dim3(2048/32, 2048/32), dim3(32, 8)>>>(Wo, 2048, 2048, 3);
    rope_table_kernel<<<(S_*64 + 255)/256, 256>>>();

    // projections (RoPE fused for Q/K; all emit bf16 hi/lo)
    mm_mma<<<dim3(16, 32), 256, MM_SMEM>>>(nullptr, 2048, 0, 0, 1, 2048);
    mm_mma<<<dim3(4,  32), 256, MM_SMEM>>>(nullptr, 2048, 0, 1, 2, 512);
    mm_mma<<<dim3(4,  32), 256, MM_SMEM>>>(nullptr, 2048, 0, 2, 3, 512);

    // attention (tensor-core, split-bf16)
    attn_mma<<<dim3(16, NH_, B_), 256, ATT_SMEM>>>();

    // output projection
    mm_mma<<<dim3(16, 32), 256, MM_SMEM>>>(out, 2048, 1, 3, 0, 2048);
}